// round 2
// baseline (speedup 1.0000x reference)
#include <cuda_runtime.h>
#include <cuda_bf16.h>

// Problem constants
#define BATCH   64
#define NVERTS  1220
#define NSUB    305
#define CS      256      // channels
#define HS      56
#define WS      56
#define HW      (HS*WS)  // 3136
#define TILE_P  64       // points per block
#define NTILES  5        // ceil(305/64)
#define CPAD    257      // pf row stride (bank-conflict padding)
#define Y0PAD   129      // y0 row stride

#define MESH_OFF 0
#define PROJ_OFF (BATCH * 5 * NSUB)   // 97600

// smem layout (floats):
//   pf   [TILE_P][CPAD]      = 16448
//   y0s  [TILE_P][Y0PAD]     =  8256
//   sx0  [TILE_P] (int)      =    64
//   sy0  [TILE_P] (int)      =    64
//   swx  [TILE_P]            =    64
//   swy  [TILE_P]            =    64
#define SMEM_FLOATS (TILE_P*CPAD + TILE_P*Y0PAD + 4*TILE_P)
#define SMEM_BYTES  (SMEM_FLOATS * 4)

__global__ __launch_bounds__(256, 2)
void laf_fused_kernel(const float* __restrict__ p,
                      const float* __restrict__ extr,
                      const float* __restrict__ intr,
                      const float* __restrict__ s_feat,
                      const int*   __restrict__ sub_idx,
                      const float* __restrict__ W0, const float* __restrict__ b0,
                      const float* __restrict__ W1, const float* __restrict__ b1,
                      const float* __restrict__ W2, const float* __restrict__ b2,
                      float* __restrict__ out)
{
    extern __shared__ float smem[];
    float* pf  = smem;                         // [TILE_P][CPAD]
    float* y0s = pf + TILE_P * CPAD;           // [TILE_P][Y0PAD]
    int*   sx0 = (int*)(y0s + TILE_P * Y0PAD); // [TILE_P]
    int*   sy0 = sx0 + TILE_P;
    float* swx = (float*)(sy0 + TILE_P);
    float* swy = swx + TILE_P;

    const int tile = blockIdx.x;   // 0..NTILES-1
    const int b    = blockIdx.y;   // 0..BATCH-1
    const int tid  = threadIdx.x;  // 0..255

    // ---------------- Phase 0: projection (threads 0..63, one point each) ----
    if (tid < TILE_P) {
        const int n = tile * TILE_P + tid;
        if (n < NSUB) {
            const int vid = sub_idx[n];
            const float ptx = p[(b * NVERTS + vid) * 3 + 0];
            const float pty = p[(b * NVERTS + vid) * 3 + 1];
            const float ptz = p[(b * NVERTS + vid) * 3 + 2];
            const float* E = extr + b * 16;
            float cam[4];
            #pragma unroll
            for (int g = 0; g < 4; g++)
                cam[g] = ptx * E[0*4+g] + pty * E[1*4+g] + ptz * E[2*4+g] + E[3*4+g];
            const float* I = intr + b * 12;
            float img[3];
            #pragma unroll
            for (int g = 0; g < 3; g++)
                img[g] = cam[0]*I[0*3+g] + cam[1]*I[1*3+g] + cam[2]*I[2*3+g] + cam[3]*I[3*3+g];
            const float invz = 1.0f / img[2];
            const float px = img[0] * invz;
            const float py = img[1] * invz;

            // p_proj_2d output
            out[PROJ_OFF + (b * NSUB + n) * 2 + 0] = px;
            out[PROJ_OFF + (b * NSUB + n) * 2 + 1] = py;

            // grid coords (match reference arithmetic order)
            const float gx = px / 224.0f * 2.0f - 1.0f;
            const float gy = py / 224.0f * 2.0f - 1.0f;
            const float x = (gx + 1.0f) * 0.5f * (float)(WS - 1);
            const float y = (gy + 1.0f) * 0.5f * (float)(HS - 1);
            const float x0f = floorf(x);
            const float y0f = floorf(y);
            sx0[tid] = (int)x0f;
            sy0[tid] = (int)y0f;
            swx[tid] = x - x0f;
            swy[tid] = y - y0f;
        } else {
            sx0[tid] = -100000;  // all corners invalid -> pf = 0
            sy0[tid] = -100000;
            swx[tid] = 0.0f;
            swy[tid] = 0.0f;
        }
    }
    __syncthreads();

    // ---------------- Phase 1: bilinear gather into smem ---------------------
    // thread tid = channel c (exactly 256 channels)
    {
        const int c = tid;
        const float* F = s_feat + (size_t)(b * CS + c) * HW;
        #pragma unroll 4
        for (int pp = 0; pp < TILE_P; pp++) {
            const int x0 = sx0[pp];
            const int y0 = sy0[pp];
            const float wx1 = swx[pp];
            const float wy1 = swy[pp];
            const float wx0 = 1.0f - wx1;
            const float wy0 = 1.0f - wy1;
            const bool vx0 = (x0 >= 0) && (x0 <= WS - 1);
            const bool vx1 = (x0 + 1 >= 0) && (x0 + 1 <= WS - 1);
            const bool vy0 = (y0 >= 0) && (y0 <= HS - 1);
            const bool vy1 = (y0 + 1 >= 0) && (y0 + 1 <= HS - 1);
            float v = 0.0f;
            if (vy0) {
                const float* row = F + y0 * WS;
                if (vx0) v += wx0 * wy0 * __ldg(row + x0);
                if (vx1) v += wx1 * wy0 * __ldg(row + x0 + 1);
            }
            if (vy1) {
                const float* row = F + (y0 + 1) * WS;
                if (vx0) v += wx0 * wy1 * __ldg(row + x0);
                if (vx1) v += wx1 * wy1 * __ldg(row + x0 + 1);
            }
            pf[pp * CPAD + c] = v;
        }
    }
    __syncthreads();

    // ---------------- Phase 2: layer 0  (256 -> 128, leaky_relu) -------------
    // thread -> 4 outputs x 8 points
    {
        const int og = tid >> 3;      // 0..31 : o base = og*4
        const int pg = tid & 7;       // 0..7  : p base = pg*8
        float acc[4][8];
        #pragma unroll
        for (int i = 0; i < 4; i++)
            #pragma unroll
            for (int j = 0; j < 8; j++) acc[i][j] = 0.0f;

        const float* w0r = W0 + (og * 4) * 256;
        #pragma unroll 4
        for (int c = 0; c < 256; c++) {
            float w_[4];
            #pragma unroll
            for (int i = 0; i < 4; i++) w_[i] = __ldg(w0r + i * 256 + c);
            float pv[8];
            #pragma unroll
            for (int j = 0; j < 8; j++) pv[j] = pf[(pg * 8 + j) * CPAD + c];
            #pragma unroll
            for (int i = 0; i < 4; i++)
                #pragma unroll
                for (int j = 0; j < 8; j++)
                    acc[i][j] = fmaf(w_[i], pv[j], acc[i][j]);
        }
        #pragma unroll
        for (int i = 0; i < 4; i++) {
            const float bias = __ldg(b0 + og * 4 + i);
            #pragma unroll
            for (int j = 0; j < 8; j++) {
                float v = acc[i][j] + bias;
                v = (v >= 0.0f) ? v : 0.01f * v;
                y0s[(pg * 8 + j) * Y0PAD + (og * 4 + i)] = v;
            }
        }
    }
    __syncthreads();

    // ---------------- Phase 3: layer 1  (128+256 -> 64, leaky_relu) ----------
    // thread -> 4 outputs x 4 points
    float y1acc[4][4];
    int l1_og, l1_pg;
    {
        l1_og = tid >> 4;     // 0..15 : o base = og*4
        l1_pg = tid & 15;     // 0..15 : p base = pg*4
        #pragma unroll
        for (int i = 0; i < 4; i++)
            #pragma unroll
            for (int j = 0; j < 4; j++) y1acc[i][j] = 0.0f;

        const float* w1r = W1 + (l1_og * 4) * 384;
        // first 128 inputs: y0
        #pragma unroll 4
        for (int k = 0; k < 128; k++) {
            float w_[4];
            #pragma unroll
            for (int i = 0; i < 4; i++) w_[i] = __ldg(w1r + i * 384 + k);
            float pv[4];
            #pragma unroll
            for (int j = 0; j < 4; j++) pv[j] = y0s[(l1_pg * 4 + j) * Y0PAD + k];
            #pragma unroll
            for (int i = 0; i < 4; i++)
                #pragma unroll
                for (int j = 0; j < 4; j++)
                    y1acc[i][j] = fmaf(w_[i], pv[j], y1acc[i][j]);
        }
        // next 256 inputs: point_feat
        #pragma unroll 4
        for (int k = 0; k < 256; k++) {
            float w_[4];
            #pragma unroll
            for (int i = 0; i < 4; i++) w_[i] = __ldg(w1r + i * 384 + 128 + k);
            float pv[4];
            #pragma unroll
            for (int j = 0; j < 4; j++) pv[j] = pf[(l1_pg * 4 + j) * CPAD + k];
            #pragma unroll
            for (int i = 0; i < 4; i++)
                #pragma unroll
                for (int j = 0; j < 4; j++)
                    y1acc[i][j] = fmaf(w_[i], pv[j], y1acc[i][j]);
        }
    }
    __syncthreads();  // done reading y0s; now overwrite with y1

    {
        #pragma unroll
        for (int i = 0; i < 4; i++) {
            const float bias = __ldg(b1 + l1_og * 4 + i);
            #pragma unroll
            for (int j = 0; j < 4; j++) {
                float v = y1acc[i][j] + bias;
                v = (v >= 0.0f) ? v : 0.01f * v;
                y0s[(l1_pg * 4 + j) * Y0PAD + (l1_og * 4 + i)] = v;  // y1 stored in y0s[:, 0:64]
            }
        }
    }
    __syncthreads();

    // ---------------- Phase 4: layer 2  (64+256 -> 5, relu) ------------------
    // threads 0..63: one point each, all 5 outputs
    if (tid < TILE_P) {
        const int n = tile * TILE_P + tid;
        if (n < NSUB) {
            float acc[5];
            #pragma unroll
            for (int o = 0; o < 5; o++) acc[o] = __ldg(b2 + o);
            // first 64 inputs: y1
            #pragma unroll 4
            for (int k = 0; k < 64; k++) {
                const float v = y0s[tid * Y0PAD + k];
                #pragma unroll
                for (int o = 0; o < 5; o++)
                    acc[o] = fmaf(__ldg(W2 + o * 320 + k), v, acc[o]);
            }
            // next 256 inputs: point_feat
            #pragma unroll 4
            for (int k = 0; k < 256; k++) {
                const float v = pf[tid * CPAD + k];
                #pragma unroll
                for (int o = 0; o < 5; o++)
                    acc[o] = fmaf(__ldg(W2 + o * 320 + 64 + k), v, acc[o]);
            }
            #pragma unroll
            for (int o = 0; o < 5; o++) {
                float v = acc[o];
                v = (v > 0.0f) ? v : 0.0f;
                out[MESH_OFF + b * (5 * NSUB) + o * NSUB + n] = v;
            }
        }
    }
}

extern "C" void kernel_launch(void* const* d_in, const int* in_sizes, int n_in,
                              void* d_out, int out_size)
{
    const float* p       = (const float*)d_in[0];
    const float* extr    = (const float*)d_in[1];
    const float* intr    = (const float*)d_in[2];
    // d_in[3] = bbox (unused)
    const float* s_feat  = (const float*)d_in[4];
    const int*   sub_idx = (const int*)  d_in[5];
    const float* W0      = (const float*)d_in[6];
    const float* b0      = (const float*)d_in[7];
    const float* W1      = (const float*)d_in[8];
    const float* b1      = (const float*)d_in[9];
    const float* W2      = (const float*)d_in[10];
    const float* b2      = (const float*)d_in[11];
    float* out = (float*)d_out;

    cudaFuncSetAttribute(laf_fused_kernel,
                         cudaFuncAttributeMaxDynamicSharedMemorySize, SMEM_BYTES);

    dim3 grid(NTILES, BATCH);
    laf_fused_kernel<<<grid, 256, SMEM_BYTES>>>(
        p, extr, intr, s_feat, sub_idx, W0, b0, W1, b1, W2, b2, out);
}

// round 4
// speedup vs baseline: 1.1550x; 1.1550x over previous
#include <cuda_runtime.h>

// Problem constants
#define BATCH   64
#define NVERTS  1220
#define NSUB    305
#define CS      256
#define HS      56
#define WS      56
#define HW      (HS*WS)   // 3136
#define TILE_P  64
#define NTILES  5
#define PPAD    68        // point-dim stride (16B aligned, conflict-mitigating)

#define MESH_OFF 0
#define PROJ_OFF (BATCH * 5 * NSUB)   // 97600

// Transposed feature map scratch: [B][HW][C]  (~205 MB __device__ scratch)
__device__ float g_sfT[(size_t)BATCH * HW * CS];

typedef unsigned long long ull;

__device__ __forceinline__ ull pack2(float a, float b) {
    ull r; asm("mov.b64 %0, {%1, %2};" : "=l"(r) : "f"(a), "f"(b)); return r;
}
__device__ __forceinline__ void unpack2(ull v, float& a, float& b) {
    asm("mov.b64 {%0, %1}, %2;" : "=f"(a), "=f"(b) : "l"(v));
}
__device__ __forceinline__ ull ffma2(ull a, ull b, ull c) {
    ull d; asm("fma.rn.f32x2 %0, %1, %2, %3;" : "=l"(d) : "l"(a), "l"(b), "l"(c)); return d;
}

// ---------------------------------------------------------------------------
// Kernel 1: transpose [B][C][HW] -> [B][HW][C]
// ---------------------------------------------------------------------------
__global__ __launch_bounds__(256)
void transpose_kernel(const float* __restrict__ in)
{
    __shared__ float tile[32][33];
    const int hw0 = blockIdx.x * 32;     // 98 tiles (3136/32)
    const int c0  = blockIdx.y * 32;     // 8 tiles  (256/32)
    const int b   = blockIdx.z;
    const int tx  = threadIdx.x;
    const int ty  = threadIdx.y;

    const float* src = in + ((size_t)b * CS + c0) * HW + hw0;
    #pragma unroll
    for (int i = ty; i < 32; i += 8)
        tile[i][tx] = src[(size_t)i * HW + tx];      // row c0+i, col hw0+tx
    __syncthreads();
    float* dst = g_sfT + ((size_t)b * HW + hw0) * CS + c0;
    #pragma unroll
    for (int i = ty; i < 32; i += 8)
        dst[(size_t)i * CS + tx] = tile[tx][i];      // [b][hw0+i][c0+tx]
}

// ---------------------------------------------------------------------------
// Kernel 2: fused projection + coalesced gather + MLP
// smem (floats): pf[256][PPAD] | y0T[128][PPAD] | w2s[1600] | coords
// ---------------------------------------------------------------------------
#define PF_FLOATS   (CS * PPAD)          // 17408
#define Y0_FLOATS   (128 * PPAD)         // 8704
#define W2_FLOATS   (5 * 320)            // 1600
#define SMEM_FLOATS (PF_FLOATS + Y0_FLOATS + W2_FLOATS + 4 * TILE_P)
#define SMEM_BYTES  (SMEM_FLOATS * 4)

__global__ __launch_bounds__(256, 2)
void laf_fused_kernel(const float* __restrict__ p,
                      const float* __restrict__ extr,
                      const float* __restrict__ intr,
                      const int*   __restrict__ sub_idx,
                      const float* __restrict__ W0, const float* __restrict__ b0,
                      const float* __restrict__ W1, const float* __restrict__ b1,
                      const float* __restrict__ W2, const float* __restrict__ b2,
                      float* __restrict__ out)
{
    extern __shared__ float smem[];
    float* pf  = smem;                      // [c][PPAD]
    float* y0T = pf + PF_FLOATS;            // [o][PPAD]
    float* w2s = y0T + Y0_FLOATS;           // [5][320]
    int*   sx0 = (int*)(w2s + W2_FLOATS);
    int*   sy0 = sx0 + TILE_P;
    float* swx = (float*)(sy0 + TILE_P);
    float* swy = swx + TILE_P;

    const int tile = blockIdx.x;
    const int b    = blockIdx.y;
    const int tid  = threadIdx.x;

    // -------- W2 -> smem (coalesced, once) --------
    for (int i = tid; i < W2_FLOATS; i += 256)
        w2s[i] = __ldg(W2 + i);

    // -------- Phase 0: projection (threads 0..63) --------
    if (tid < TILE_P) {
        const int n = tile * TILE_P + tid;
        if (n < NSUB) {
            const int vid = sub_idx[n];
            const float ptx = p[(b * NVERTS + vid) * 3 + 0];
            const float pty = p[(b * NVERTS + vid) * 3 + 1];
            const float ptz = p[(b * NVERTS + vid) * 3 + 2];
            const float* E = extr + b * 16;
            float cam[4];
            #pragma unroll
            for (int g = 0; g < 4; g++)
                cam[g] = ptx * E[0*4+g] + pty * E[1*4+g] + ptz * E[2*4+g] + E[3*4+g];
            const float* I = intr + b * 12;
            float img[3];
            #pragma unroll
            for (int g = 0; g < 3; g++)
                img[g] = cam[0]*I[0*3+g] + cam[1]*I[1*3+g] + cam[2]*I[2*3+g] + cam[3]*I[3*3+g];
            const float px = img[0] / img[2];
            const float py = img[1] / img[2];

            out[PROJ_OFF + (b * NSUB + n) * 2 + 0] = px;
            out[PROJ_OFF + (b * NSUB + n) * 2 + 1] = py;

            const float gx = px / 224.0f * 2.0f - 1.0f;
            const float gy = py / 224.0f * 2.0f - 1.0f;
            const float x = (gx + 1.0f) * 0.5f * (float)(WS - 1);
            const float y = (gy + 1.0f) * 0.5f * (float)(HS - 1);
            const float x0f = floorf(x);
            const float y0f = floorf(y);
            sx0[tid] = (int)x0f;
            sy0[tid] = (int)y0f;
            swx[tid] = x - x0f;
            swy[tid] = y - y0f;
        } else {
            sx0[tid] = -100000;
            sy0[tid] = -100000;
            swx[tid] = 0.0f;
            swy[tid] = 0.0f;
        }
    }
    __syncthreads();

    // -------- Phase 1: coalesced bilinear gather (thread = channel) --------
    {
        const int c = tid;
        const float* Fb = g_sfT + (size_t)b * HW * CS + c;
        #pragma unroll 4
        for (int pp = 0; pp < TILE_P; pp++) {
            const int x0 = sx0[pp];
            const int y0 = sy0[pp];
            const float wx1 = swx[pp];
            const float wy1 = swy[pp];
            const float wx0 = 1.0f - wx1;
            const float wy0 = 1.0f - wy1;
            const bool vx0 = (x0 >= 0) && (x0 < WS);
            const bool vx1 = (x0 >= -1) && (x0 < WS - 1);
            const bool vy0 = (y0 >= 0) && (y0 < HS);
            const bool vy1 = (y0 >= -1) && (y0 < HS - 1);
            const long off = (long)(y0 * WS + x0) * CS;
            float v = 0.0f;
            if (vy0) {
                if (vx0) v = fmaf(wx0 * wy0, __ldg(Fb + off), v);
                if (vx1) v = fmaf(wx1 * wy0, __ldg(Fb + off + CS), v);
            }
            if (vy1) {
                if (vx0) v = fmaf(wx0 * wy1, __ldg(Fb + off + WS * CS), v);
                if (vx1) v = fmaf(wx1 * wy1, __ldg(Fb + off + WS * CS + CS), v);
            }
            pf[c * PPAD + pp] = v;
        }
    }
    __syncthreads();

    // -------- Phase 2: layer 0 (256 -> 128, leaky), f32x2 packed --------
    // thread = (og 0..31) x (pg 0..7): 4 outputs x 8 points (4 pairs)
    {
        const int og = tid >> 3;
        const int pg = tid & 7;
        ull acc[4][4];
        #pragma unroll
        for (int i = 0; i < 4; i++)
            #pragma unroll
            for (int j = 0; j < 4; j++) acc[i][j] = 0ULL;

        const float* w0r = W0 + (og * 4) * 256;
        const float* pvb = pf + pg * 8;

        for (int c4 = 0; c4 < 256; c4 += 4) {
            float wbuf[4][4];
            #pragma unroll
            for (int i = 0; i < 4; i++)
                *(float4*)wbuf[i] = __ldg((const float4*)(w0r + i * 256 + c4));
            #pragma unroll
            for (int dc = 0; dc < 4; dc++) {
                const float4 pa = *(const float4*)(pvb + (c4 + dc) * PPAD);
                const float4 pb = *(const float4*)(pvb + (c4 + dc) * PPAD + 4);
                const ull p01 = pack2(pa.x, pa.y);
                const ull p23 = pack2(pa.z, pa.w);
                const ull p45 = pack2(pb.x, pb.y);
                const ull p67 = pack2(pb.z, pb.w);
                #pragma unroll
                for (int i = 0; i < 4; i++) {
                    const ull w2p = pack2(wbuf[i][dc], wbuf[i][dc]);
                    acc[i][0] = ffma2(w2p, p01, acc[i][0]);
                    acc[i][1] = ffma2(w2p, p23, acc[i][1]);
                    acc[i][2] = ffma2(w2p, p45, acc[i][2]);
                    acc[i][3] = ffma2(w2p, p67, acc[i][3]);
                }
            }
        }
        #pragma unroll
        for (int i = 0; i < 4; i++) {
            const int o = og * 4 + i;
            const float bias = __ldg(b0 + o);
            float f[8];
            #pragma unroll
            for (int j = 0; j < 4; j++) unpack2(acc[i][j], f[2*j], f[2*j+1]);
            #pragma unroll
            for (int j = 0; j < 8; j++) {
                float v = f[j] + bias;
                f[j] = (v >= 0.0f) ? v : 0.01f * v;
            }
            float* dst = y0T + o * PPAD + pg * 8;
            *(float4*)(dst)     = make_float4(f[0], f[1], f[2], f[3]);
            *(float4*)(dst + 4) = make_float4(f[4], f[5], f[6], f[7]);
        }
    }
    __syncthreads();

    // -------- Phase 3: layer 1 (128+256 -> 64, leaky), f32x2 packed --------
    // thread = (og 0..31) x (pg 0..7): 2 outputs x 8 points (4 pairs)
    ull acc1[2][4];
    int l1_og, l1_pg;
    {
        l1_og = tid >> 3;
        l1_pg = tid & 7;
        #pragma unroll
        for (int i = 0; i < 2; i++)
            #pragma unroll
            for (int j = 0; j < 4; j++) acc1[i][j] = 0ULL;

        const float* w1r = W1 + (l1_og * 2) * 384;
        const float* pvb0 = y0T + l1_pg * 8;
        const float* pvb1 = pf  + l1_pg * 8;

        // first 128 inputs: y0
        for (int c4 = 0; c4 < 128; c4 += 4) {
            float wbuf[2][4];
            #pragma unroll
            for (int i = 0; i < 2; i++)
                *(float4*)wbuf[i] = __ldg((const float4*)(w1r + i * 384 + c4));
            #pragma unroll
            for (int dc = 0; dc < 4; dc++) {
                const float4 pa = *(const float4*)(pvb0 + (c4 + dc) * PPAD);
                const float4 pb = *(const float4*)(pvb0 + (c4 + dc) * PPAD + 4);
                const ull p01 = pack2(pa.x, pa.y);
                const ull p23 = pack2(pa.z, pa.w);
                const ull p45 = pack2(pb.x, pb.y);
                const ull p67 = pack2(pb.z, pb.w);
                #pragma unroll
                for (int i = 0; i < 2; i++) {
                    const ull w2p = pack2(wbuf[i][dc], wbuf[i][dc]);
                    acc1[i][0] = ffma2(w2p, p01, acc1[i][0]);
                    acc1[i][1] = ffma2(w2p, p23, acc1[i][1]);
                    acc1[i][2] = ffma2(w2p, p45, acc1[i][2]);
                    acc1[i][3] = ffma2(w2p, p67, acc1[i][3]);
                }
            }
        }
        // next 256 inputs: point_feat
        for (int c4 = 0; c4 < 256; c4 += 4) {
            float wbuf[2][4];
            #pragma unroll
            for (int i = 0; i < 2; i++)
                *(float4*)wbuf[i] = __ldg((const float4*)(w1r + i * 384 + 128 + c4));
            #pragma unroll
            for (int dc = 0; dc < 4; dc++) {
                const float4 pa = *(const float4*)(pvb1 + (c4 + dc) * PPAD);
                const float4 pb = *(const float4*)(pvb1 + (c4 + dc) * PPAD + 4);
                const ull p01 = pack2(pa.x, pa.y);
                const ull p23 = pack2(pa.z, pa.w);
                const ull p45 = pack2(pb.x, pb.y);
                const ull p67 = pack2(pb.z, pb.w);
                #pragma unroll
                for (int i = 0; i < 2; i++) {
                    const ull w2p = pack2(wbuf[i][dc], wbuf[i][dc]);
                    acc1[i][0] = ffma2(w2p, p01, acc1[i][0]);
                    acc1[i][1] = ffma2(w2p, p23, acc1[i][1]);
                    acc1[i][2] = ffma2(w2p, p45, acc1[i][2]);
                    acc1[i][3] = ffma2(w2p, p67, acc1[i][3]);
                }
            }
        }
    }
    __syncthreads();   // everyone done READING y0T

    {
        #pragma unroll
        for (int i = 0; i < 2; i++) {
            const int o = l1_og * 2 + i;
            const float bias = __ldg(b1 + o);
            float f[8];
            #pragma unroll
            for (int j = 0; j < 4; j++) unpack2(acc1[i][j], f[2*j], f[2*j+1]);
            #pragma unroll
            for (int j = 0; j < 8; j++) {
                float v = f[j] + bias;
                f[j] = (v >= 0.0f) ? v : 0.01f * v;
            }
            float* dst = y0T + o * PPAD + l1_pg * 8;   // y1 overwrites rows 0..63
            *(float4*)(dst)     = make_float4(f[0], f[1], f[2], f[3]);
            *(float4*)(dst + 4) = make_float4(f[4], f[5], f[6], f[7]);
        }
    }
    __syncthreads();

    // -------- Phase 4: layer 2 (64+256 -> 5, relu) --------
    if (tid < TILE_P) {
        const int n = tile * TILE_P + tid;
        if (n < NSUB) {
            float acc[5];
            #pragma unroll
            for (int o = 0; o < 5; o++) acc[o] = __ldg(b2 + o);
            #pragma unroll 4
            for (int k = 0; k < 64; k++) {
                const float v = y0T[k * PPAD + tid];
                #pragma unroll
                for (int o = 0; o < 5; o++)
                    acc[o] = fmaf(w2s[o * 320 + k], v, acc[o]);
            }
            #pragma unroll 4
            for (int k = 0; k < 256; k++) {
                const float v = pf[k * PPAD + tid];
                #pragma unroll
                for (int o = 0; o < 5; o++)
                    acc[o] = fmaf(w2s[o * 320 + 64 + k], v, acc[o]);
            }
            #pragma unroll
            for (int o = 0; o < 5; o++) {
                const float v = (acc[o] > 0.0f) ? acc[o] : 0.0f;
                out[MESH_OFF + b * (5 * NSUB) + o * NSUB + n] = v;
            }
        }
    }
}

extern "C" void kernel_launch(void* const* d_in, const int* in_sizes, int n_in,
                              void* d_out, int out_size)
{
    const float* p       = (const float*)d_in[0];
    const float* extr    = (const float*)d_in[1];
    const float* intr    = (const float*)d_in[2];
    // d_in[3] = bbox (unused)
    const float* s_feat  = (const float*)d_in[4];
    const int*   sub_idx = (const int*)  d_in[5];
    const float* W0      = (const float*)d_in[6];
    const float* b0      = (const float*)d_in[7];
    const float* W1      = (const float*)d_in[8];
    const float* b1      = (const float*)d_in[9];
    const float* W2      = (const float*)d_in[10];
    const float* b2      = (const float*)d_in[11];
    float* out = (float*)d_out;

    // Unconditional (no static state — kernel_launch must be stateless/deterministic)
    cudaFuncSetAttribute(laf_fused_kernel,
                         cudaFuncAttributeMaxDynamicSharedMemorySize, SMEM_BYTES);

    transpose_kernel<<<dim3(HW / 32, CS / 32, BATCH), dim3(32, 8)>>>(s_feat);

    dim3 grid(NTILES, BATCH);
    laf_fused_kernel<<<grid, 256, SMEM_BYTES>>>(
        p, extr, intr, sub_idx, W0, b0, W1, b1, W2, b2, out);
}

// round 6
// speedup vs baseline: 1.8436x; 1.5962x over previous
#include <cuda_runtime.h>

// Problem constants
#define BATCH   64
#define NVERTS  1220
#define NSUB    305
#define CS      256
#define HS      56
#define WS      56
#define HW      (HS*WS)   // 3136
#define TILE_P  32
#define NTILES  10        // ceil(305/32)
#define PPAD    36        // point-dim stride (16B aligned)

#define MESH_OFF 0
#define PROJ_OFF (BATCH * 5 * NSUB)   // 97600

// Transposed feature map scratch: [B][HW][C]  (~205 MB __device__ scratch)
__device__ float g_sfT[(size_t)BATCH * HW * CS];

typedef unsigned long long ull;

__device__ __forceinline__ ull pack2(float a, float b) {
    ull r; asm("mov.b64 %0, {%1, %2};" : "=l"(r) : "f"(a), "f"(b)); return r;
}
__device__ __forceinline__ void unpack2(ull v, float& a, float& b) {
    asm("mov.b64 {%0, %1}, %2;" : "=f"(a), "=f"(b) : "l"(v));
}
__device__ __forceinline__ ull ffma2(ull a, ull b, ull c) {
    ull d; asm("fma.rn.f32x2 %0, %1, %2, %3;" : "=l"(d) : "l"(a), "l"(b), "l"(c)); return d;
}

// ---------------------------------------------------------------------------
// Kernel 1: transpose [B][C][HW] -> [B][HW][C], fully vectorized (128b ld/st)
// tile: 32 channels x 32 hw. Block 256 threads, 1 float4 in + 1 float4 out each.
// ---------------------------------------------------------------------------
__global__ __launch_bounds__(256)
void transpose_kernel(const float* __restrict__ in)
{
    __shared__ float tile[32][33];
    const int hw0 = blockIdx.x * 32;     // 98
    const int c0  = blockIdx.y * 32;     // 8
    const int b   = blockIdx.z;          // 64
    const int t   = threadIdx.x;
    const int row = t >> 3;              // 0..31
    const int q   = t & 7;               // 0..7

    // Load: channel row (c0+row), 4 hw values  [LDG.128, coalesced]
    const float4 v = *(const float4*)(in + ((size_t)(b * CS + c0 + row)) * HW + hw0 + q * 4);
    tile[row][q * 4 + 0] = v.x;   // bank = (row + 4q) mod 32 -> permutation, conflict-free
    tile[row][q * 4 + 1] = v.y;
    tile[row][q * 4 + 2] = v.z;
    tile[row][q * 4 + 3] = v.w;
    __syncthreads();

    // Store: hw row (hw0+row), 4 channels     [STG.128, coalesced 128B/8 lanes]
    float4 w;
    w.x = tile[q * 4 + 0][row];   // bank = (4q + k + row) mod 32 -> permutation
    w.y = tile[q * 4 + 1][row];
    w.z = tile[q * 4 + 2][row];
    w.w = tile[q * 4 + 3][row];
    *(float4*)(g_sfT + ((size_t)(b * HW + hw0 + row)) * CS + c0 + q * 4) = w;
}

// ---------------------------------------------------------------------------
// Kernel 2: fused projection + coalesced gather + MLP (32 points / block)
// smem (floats): pf[256][PPAD] | y0T[128][PPAD] | w2s[1600] | coords
// ---------------------------------------------------------------------------
#define PF_FLOATS   (CS * PPAD)          // 9216
#define Y0_FLOATS   (128 * PPAD)         // 4608
#define W2_FLOATS   (5 * 320)            // 1600
#define SMEM_FLOATS (PF_FLOATS + Y0_FLOATS + W2_FLOATS + 4 * TILE_P)
#define SMEM_BYTES  (SMEM_FLOATS * 4)    // ~62.2 KB -> 3 CTAs/SM

__global__ __launch_bounds__(256, 3)
void laf_fused_kernel(const float* __restrict__ p,
                      const float* __restrict__ extr,
                      const float* __restrict__ intr,
                      const int*   __restrict__ sub_idx,
                      const float* __restrict__ W0, const float* __restrict__ b0,
                      const float* __restrict__ W1, const float* __restrict__ b1,
                      const float* __restrict__ W2, const float* __restrict__ b2,
                      float* __restrict__ out)
{
    extern __shared__ float smem[];
    float* pf  = smem;                      // [c][PPAD]
    float* y0T = pf + PF_FLOATS;            // [o][PPAD]
    float* w2s = y0T + Y0_FLOATS;           // [5][320]
    int*   sx0 = (int*)(w2s + W2_FLOATS);
    int*   sy0 = sx0 + TILE_P;
    float* swx = (float*)(sy0 + TILE_P);
    float* swy = swx + TILE_P;

    const int tile = blockIdx.x;
    const int b    = blockIdx.y;
    const int tid  = threadIdx.x;

    // -------- W2 -> smem --------
    for (int i = tid; i < W2_FLOATS; i += 256)
        w2s[i] = __ldg(W2 + i);

    // -------- Phase 0: projection (threads 0..31) --------
    if (tid < TILE_P) {
        const int n = tile * TILE_P + tid;
        if (n < NSUB) {
            const int vid = sub_idx[n];
            const float ptx = p[(b * NVERTS + vid) * 3 + 0];
            const float pty = p[(b * NVERTS + vid) * 3 + 1];
            const float ptz = p[(b * NVERTS + vid) * 3 + 2];
            const float* E = extr + b * 16;
            float cam[4];
            #pragma unroll
            for (int g = 0; g < 4; g++)
                cam[g] = ptx * E[0*4+g] + pty * E[1*4+g] + ptz * E[2*4+g] + E[3*4+g];
            const float* I = intr + b * 12;
            float img[3];
            #pragma unroll
            for (int g = 0; g < 3; g++)
                img[g] = cam[0]*I[0*3+g] + cam[1]*I[1*3+g] + cam[2]*I[2*3+g] + cam[3]*I[3*3+g];
            const float px = img[0] / img[2];
            const float py = img[1] / img[2];

            out[PROJ_OFF + (b * NSUB + n) * 2 + 0] = px;
            out[PROJ_OFF + (b * NSUB + n) * 2 + 1] = py;

            const float gx = px / 224.0f * 2.0f - 1.0f;
            const float gy = py / 224.0f * 2.0f - 1.0f;
            const float x = (gx + 1.0f) * 0.5f * (float)(WS - 1);
            const float y = (gy + 1.0f) * 0.5f * (float)(HS - 1);
            const float x0f = floorf(x);
            const float y0f = floorf(y);
            sx0[tid] = (int)x0f;
            sy0[tid] = (int)y0f;
            swx[tid] = x - x0f;
            swy[tid] = y - y0f;
        } else {
            sx0[tid] = -100000;
            sy0[tid] = -100000;
            swx[tid] = 0.0f;
            swy[tid] = 0.0f;
        }
    }
    __syncthreads();

    // -------- Phase 1: coalesced bilinear gather (thread = channel) --------
    {
        const int c = tid;
        const float* Fb = g_sfT + (size_t)b * HW * CS + c;
        #pragma unroll 4
        for (int pp = 0; pp < TILE_P; pp++) {
            const int x0 = sx0[pp];
            const int y0 = sy0[pp];
            const float wx1 = swx[pp];
            const float wy1 = swy[pp];
            const float wx0 = 1.0f - wx1;
            const float wy0 = 1.0f - wy1;
            const bool vx0 = (x0 >= 0) && (x0 < WS);
            const bool vx1 = (x0 >= -1) && (x0 < WS - 1);
            const bool vy0 = (y0 >= 0) && (y0 < HS);
            const bool vy1 = (y0 >= -1) && (y0 < HS - 1);
            const long off = (long)(y0 * WS + x0) * CS;
            float v = 0.0f;
            if (vy0) {
                if (vx0) v = fmaf(wx0 * wy0, __ldg(Fb + off), v);
                if (vx1) v = fmaf(wx1 * wy0, __ldg(Fb + off + CS), v);
            }
            if (vy1) {
                if (vx0) v = fmaf(wx0 * wy1, __ldg(Fb + off + WS * CS), v);
                if (vx1) v = fmaf(wx1 * wy1, __ldg(Fb + off + WS * CS + CS), v);
            }
            pf[c * PPAD + pp] = v;
        }
    }
    __syncthreads();

    // -------- Phase 2: layer 0 (256 -> 128, leaky), f32x2 packed --------
    // thread = (og 0..31) x (pg 0..7): 4 outputs x 4 points (2 pairs)
    {
        const int og = tid >> 3;
        const int pg = tid & 7;
        ull acc[4][2];
        #pragma unroll
        for (int i = 0; i < 4; i++) { acc[i][0] = 0ULL; acc[i][1] = 0ULL; }

        const float* w0r = W0 + (og * 4) * 256;
        const float* pvb = pf + pg * 4;

        for (int c4 = 0; c4 < 256; c4 += 4) {
            float wbuf[4][4];
            #pragma unroll
            for (int i = 0; i < 4; i++)
                *(float4*)wbuf[i] = __ldg((const float4*)(w0r + i * 256 + c4));
            #pragma unroll
            for (int dc = 0; dc < 4; dc++) {
                const float4 pa = *(const float4*)(pvb + (c4 + dc) * PPAD);
                const ull p01 = pack2(pa.x, pa.y);
                const ull p23 = pack2(pa.z, pa.w);
                #pragma unroll
                for (int i = 0; i < 4; i++) {
                    const ull w2p = pack2(wbuf[i][dc], wbuf[i][dc]);
                    acc[i][0] = ffma2(w2p, p01, acc[i][0]);
                    acc[i][1] = ffma2(w2p, p23, acc[i][1]);
                }
            }
        }
        #pragma unroll
        for (int i = 0; i < 4; i++) {
            const int o = og * 4 + i;
            const float bias = __ldg(b0 + o);
            float f[4];
            unpack2(acc[i][0], f[0], f[1]);
            unpack2(acc[i][1], f[2], f[3]);
            #pragma unroll
            for (int j = 0; j < 4; j++) {
                float v = f[j] + bias;
                f[j] = (v >= 0.0f) ? v : 0.01f * v;
            }
            *(float4*)(y0T + o * PPAD + pg * 4) = make_float4(f[0], f[1], f[2], f[3]);
        }
    }
    __syncthreads();

    // -------- Phase 3: layer 1 (128+256 -> 64, leaky), f32x2 packed --------
    // thread = (og 0..31) x (pg 0..7): 2 outputs x 4 points (2 pairs)
    ull acc1[2][2];
    int l1_og, l1_pg;
    {
        l1_og = tid >> 3;
        l1_pg = tid & 7;
        acc1[0][0] = acc1[0][1] = acc1[1][0] = acc1[1][1] = 0ULL;

        const float* w1r = W1 + (l1_og * 2) * 384;
        const float* pvb0 = y0T + l1_pg * 4;
        const float* pvb1 = pf  + l1_pg * 4;

        // first 128 inputs: y0
        for (int c4 = 0; c4 < 128; c4 += 4) {
            float wbuf[2][4];
            #pragma unroll
            for (int i = 0; i < 2; i++)
                *(float4*)wbuf[i] = __ldg((const float4*)(w1r + i * 384 + c4));
            #pragma unroll
            for (int dc = 0; dc < 4; dc++) {
                const float4 pa = *(const float4*)(pvb0 + (c4 + dc) * PPAD);
                const ull p01 = pack2(pa.x, pa.y);
                const ull p23 = pack2(pa.z, pa.w);
                #pragma unroll
                for (int i = 0; i < 2; i++) {
                    const ull w2p = pack2(wbuf[i][dc], wbuf[i][dc]);
                    acc1[i][0] = ffma2(w2p, p01, acc1[i][0]);
                    acc1[i][1] = ffma2(w2p, p23, acc1[i][1]);
                }
            }
        }
        // next 256 inputs: point_feat
        for (int c4 = 0; c4 < 256; c4 += 4) {
            float wbuf[2][4];
            #pragma unroll
            for (int i = 0; i < 2; i++)
                *(float4*)wbuf[i] = __ldg((const float4*)(w1r + i * 384 + 128 + c4));
            #pragma unroll
            for (int dc = 0; dc < 4; dc++) {
                const float4 pa = *(const float4*)(pvb1 + (c4 + dc) * PPAD);
                const ull p01 = pack2(pa.x, pa.y);
                const ull p23 = pack2(pa.z, pa.w);
                #pragma unroll
                for (int i = 0; i < 2; i++) {
                    const ull w2p = pack2(wbuf[i][dc], wbuf[i][dc]);
                    acc1[i][0] = ffma2(w2p, p01, acc1[i][0]);
                    acc1[i][1] = ffma2(w2p, p23, acc1[i][1]);
                }
            }
        }
    }
    __syncthreads();   // everyone done READING y0T

    {
        #pragma unroll
        for (int i = 0; i < 2; i++) {
            const int o = l1_og * 2 + i;
            const float bias = __ldg(b1 + o);
            float f[4];
            unpack2(acc1[i][0], f[0], f[1]);
            unpack2(acc1[i][1], f[2], f[3]);
            #pragma unroll
            for (int j = 0; j < 4; j++) {
                float v = f[j] + bias;
                f[j] = (v >= 0.0f) ? v : 0.01f * v;
            }
            *(float4*)(y0T + o * PPAD + l1_pg * 4) = make_float4(f[0], f[1], f[2], f[3]);
        }
    }
    __syncthreads();

    // -------- Phase 4: layer 2 (64+256 -> 5, relu), 160 threads --------
    // thread = (o 0..4) x (pp 0..31): one output each, conflict-free LDS
    if (tid < 160) {
        const int o  = tid >> 5;     // 0..4
        const int pp = tid & 31;     // 0..31
        const int n  = tile * TILE_P + pp;
        if (n < NSUB) {
            float acc = __ldg(b2 + o);
            const float* w2r = w2s + o * 320;
            #pragma unroll 8
            for (int k = 0; k < 64; k++)
                acc = fmaf(w2r[k], y0T[k * PPAD + pp], acc);
            #pragma unroll 8
            for (int k = 0; k < 256; k++)
                acc = fmaf(w2r[64 + k], pf[k * PPAD + pp], acc);
            out[MESH_OFF + b * (5 * NSUB) + o * NSUB + n] = (acc > 0.0f) ? acc : 0.0f;
        }
    }
}

extern "C" void kernel_launch(void* const* d_in, const int* in_sizes, int n_in,
                              void* d_out, int out_size)
{
    const float* p       = (const float*)d_in[0];
    const float* extr    = (const float*)d_in[1];
    const float* intr    = (const float*)d_in[2];
    // d_in[3] = bbox (unused)
    const float* s_feat  = (const float*)d_in[4];
    const int*   sub_idx = (const int*)  d_in[5];
    const float* W0      = (const float*)d_in[6];
    const float* b0      = (const float*)d_in[7];
    const float* W1      = (const float*)d_in[8];
    const float* b1      = (const float*)d_in[9];
    const float* W2      = (const float*)d_in[10];
    const float* b2      = (const float*)d_in[11];
    float* out = (float*)d_out;

    cudaFuncSetAttribute(laf_fused_kernel,
                         cudaFuncAttributeMaxDynamicSharedMemorySize, SMEM_BYTES);

    transpose_kernel<<<dim3(HW / 32, CS / 32, BATCH), 256>>>(s_feat);

    dim3 grid(NTILES, BATCH);
    laf_fused_kernel<<<grid, 256, SMEM_BYTES>>>(
        p, extr, intr, sub_idx, W0, b0, W1, b1, W2, b2, out);
}